// round 11
// baseline (speedup 1.0000x reference)
#include <cuda_runtime.h>
#include <math_constants.h>

#define N_DIM 512
#define KCH 32            // k-chunk per tile pass
#define NCHUNK (N_DIM / KCH)
#define PITCH 33          // conflict-free for scatter, compute, and gather
#define GROWS 64          // rows per warp-group (2 per lane -> ILP=2)
#define WPB 2             // warps per block
#define MM_BLOCKS 1184    // 8 * 148: exactly one wave

// Device-global scratch (no allocations allowed). Partials are fully
// overwritten by minmax_kernel every call -> no init kernel needed.
__device__ float g_pmn[MM_BLOCKS];
__device__ float g_pmx[MM_BLOCKS];

__global__ void minmax_kernel(const float4* __restrict__ in, long long n4) {
    float mn0 =  CUDART_INF_F, mn1 =  CUDART_INF_F;
    float mn2 =  CUDART_INF_F, mn3 =  CUDART_INF_F;
    float mx0 = -CUDART_INF_F, mx1 = -CUDART_INF_F;
    float mx2 = -CUDART_INF_F, mx3 = -CUDART_INF_F;
    long long stride = (long long)gridDim.x * blockDim.x;
    long long i = (long long)blockIdx.x * blockDim.x + threadIdx.x;
    for (; i + 3 * stride < n4; i += 4 * stride) {
        float4 v0 = in[i];
        float4 v1 = in[i + stride];
        float4 v2 = in[i + 2 * stride];
        float4 v3 = in[i + 3 * stride];
        mn0 = fminf(mn0, fminf(fminf(v0.x, v0.y), fminf(v0.z, v0.w)));
        mx0 = fmaxf(mx0, fmaxf(fmaxf(v0.x, v0.y), fmaxf(v0.z, v0.w)));
        mn1 = fminf(mn1, fminf(fminf(v1.x, v1.y), fminf(v1.z, v1.w)));
        mx1 = fmaxf(mx1, fmaxf(fmaxf(v1.x, v1.y), fmaxf(v1.z, v1.w)));
        mn2 = fminf(mn2, fminf(fminf(v2.x, v2.y), fminf(v2.z, v2.w)));
        mx2 = fmaxf(mx2, fmaxf(fmaxf(v2.x, v2.y), fmaxf(v2.z, v2.w)));
        mn3 = fminf(mn3, fminf(fminf(v3.x, v3.y), fminf(v3.z, v3.w)));
        mx3 = fmaxf(mx3, fmaxf(fmaxf(v3.x, v3.y), fmaxf(v3.z, v3.w)));
    }
    for (; i < n4; i += stride) {
        float4 v = in[i];
        mn0 = fminf(mn0, fminf(fminf(v.x, v.y), fminf(v.z, v.w)));
        mx0 = fmaxf(mx0, fmaxf(fmaxf(v.x, v.y), fmaxf(v.z, v.w)));
    }
    float mn = fminf(fminf(mn0, mn1), fminf(mn2, mn3));
    float mx = fmaxf(fmaxf(mx0, mx1), fmaxf(mx2, mx3));
    #pragma unroll
    for (int o = 16; o > 0; o >>= 1) {
        mn = fminf(mn, __shfl_xor_sync(0xFFFFFFFFu, mn, o));
        mx = fmaxf(mx, __shfl_xor_sync(0xFFFFFFFFu, mx, o));
    }
    __shared__ float smn[32], smx[32];
    int warp = threadIdx.x >> 5;
    if ((threadIdx.x & 31) == 0) { smn[warp] = mn; smx[warp] = mx; }
    __syncthreads();
    if (threadIdx.x == 0) {
        int nwarps = (blockDim.x + 31) >> 5;
        float bmn = smn[0], bmx = smx[0];
        for (int k = 1; k < nwarps; k++) {
            bmn = fminf(bmn, smn[k]);
            bmx = fmaxf(bmx, smx[k]);
        }
        g_pmn[blockIdx.x] = bmn;   // deterministic overwrite, no atomics
        g_pmx[blockIdx.x] = bmx;
    }
}

// ILP=2 warp-tiled recurrence: each warp owns a 64-row group; lane L runs
// TWO independent recurrence chains (rows L and L+32). The two chains
// interleave in the issue stream, doubling per-warp eligible issue during
// the latency-bound serial step (div chain ~60 cyc). 2048 warp-tasks,
// 64-thread blocks -> ~7 blocks/SM, near-perfect per-SM balance.
__global__ void __launch_bounds__(WPB * 32) recur_kernel(
        const float* __restrict__ in,
        const float* __restrict__ alpha,
        const float* __restrict__ beta,
        float* __restrict__ out,
        int rows) {
    __shared__ float tile_s[WPB][GROWS * PITCH];
    __shared__ float s_red[2 * WPB];
    __shared__ float s_mn, s_mx;

    const int tid  = threadIdx.x;
    const int lane = tid & 31;
    const int warp = tid >> 5;

    // ---- Prologue: every block reduces the minmax partials itself ----
    {
        float mn =  CUDART_INF_F;
        float mx = -CUDART_INF_F;
        for (int i = tid; i < MM_BLOCKS; i += WPB * 32) {
            mn = fminf(mn, g_pmn[i]);
            mx = fmaxf(mx, g_pmx[i]);
        }
        #pragma unroll
        for (int o = 16; o > 0; o >>= 1) {
            mn = fminf(mn, __shfl_xor_sync(0xFFFFFFFFu, mn, o));
            mx = fmaxf(mx, __shfl_xor_sync(0xFFFFFFFFu, mx, o));
        }
        if (lane == 0) { s_red[warp] = mn; s_red[WPB + warp] = mx; }
        __syncthreads();
        if (tid == 0) {
            float bmn = s_red[0], bmx = s_red[WPB];
            #pragma unroll
            for (int k = 1; k < WPB; k++) {
                bmn = fminf(bmn, s_red[k]);
                bmx = fmaxf(bmx, s_red[WPB + k]);
            }
            s_mn = bmn; s_mx = bmx;
        }
        __syncthreads();
    }

    const int G2   = rows / GROWS;              // 64-row groups
    const int wgid = blockIdx.x * WPB + warp;
    if (wgid >= G2) return;

    float* tile = tile_s[warp];

    const float mn  = s_mn;
    const float rng = __fsub_rn(s_mx, mn);
    const float inv = __fdiv_rn(1.0f, rng);   // == div-by-rng bitwise (verified R2/R3)
    const float a   = alpha[0];
    const float nb  = -beta[0];

    const size_t bse = (size_t)wgid * GROWS * N_DIM;
    const float* __restrict__ inw  = in  + bse;
    float* __restrict__       outw = out + bse;

    // float4 I/O pattern: lanes 0-7 cover one row's 128B chunk; 4 rows per
    // instruction; t = 0..15 covers rows 0..63.
    const int my_col4x4 = (lane & 7) * 4;
    const int row_off   = lane >> 3;

    float w0 = 1.0f;
    float w1 = 1.0f;
    const int r0 = lane;            // chain 0 row
    const int r1 = lane + 32;       // chain 1 row

    #pragma unroll 1
    for (int c = 0; c < NCHUNK; c++) {
        const int k0 = c * KCH;

        // Load chunk directly and scatter to smem (conflict-free, pitch 33).
        #pragma unroll 4
        for (int t = 0; t < 16; t++) {
            int r = t * 4 + row_off;
            float4 v = *(const float4*)(inw + (size_t)r * N_DIM + k0 + my_col4x4);
            float* p = tile + r * PITCH + my_col4x4;
            p[0] = v.x; p[1] = v.y; p[2] = v.z; p[3] = v.w;
        }
        __syncwarp();

        // Two independent serial chains per lane. out[:,k] is the pre-step w.
        //   xn = (x - mn) * inv ; w' = fma(-b, xn, w + (a / w))
        #pragma unroll
        for (int kk = 0; kk < KCH; kk++) {
            float x0 = tile[r0 * PITCH + kk];
            float x1 = tile[r1 * PITCH + kk];
            tile[r0 * PITCH + kk] = w0;
            tile[r1 * PITCH + kk] = w1;
            float xn0 = __fmul_rn(__fsub_rn(x0, mn), inv);
            float xn1 = __fmul_rn(__fsub_rn(x1, mn), inv);
            w0 = __fmaf_rn(nb, xn0, __fadd_rn(w0, __fdiv_rn(a, w0)));
            w1 = __fmaf_rn(nb, xn1, __fadd_rn(w1, __fdiv_rn(a, w1)));
        }
        __syncwarp();

        // Gather w values from smem and store as STG.128 (coalesced).
        #pragma unroll 4
        for (int t = 0; t < 16; t++) {
            int r = t * 4 + row_off;
            const float* p = tile + r * PITCH + my_col4x4;
            float4 o;
            o.x = p[0]; o.y = p[1]; o.z = p[2]; o.w = p[3];
            *(float4*)(outw + (size_t)r * N_DIM + k0 + my_col4x4) = o;
        }
        __syncwarp();
    }
}

extern "C" void kernel_launch(void* const* d_in, const int* in_sizes, int n_in,
                              void* d_out, int out_size) {
    const float* in    = (const float*)d_in[0];
    const float* alpha = (const float*)d_in[1];
    const float* beta  = (const float*)d_in[2];
    float* out = (float*)d_out;

    long long n_elems = (long long)in_sizes[0];
    long long n4 = n_elems / 4;
    int rows = (int)(n_elems / N_DIM);

    minmax_kernel<<<MM_BLOCKS, 256>>>((const float4*)in, n4);

    int groups = rows / GROWS;
    int blocks = (groups + WPB - 1) / WPB;     // 1024 for this shape
    recur_kernel<<<blocks, WPB * 32>>>(in, alpha, beta, out, rows);
}

// round 12
// speedup vs baseline: 1.2436x; 1.2436x over previous
#include <cuda_runtime.h>
#include <math_constants.h>

#define N_DIM 512
#define KCH 32            // k-chunk per tile pass
#define NCHUNK (N_DIM / KCH)
#define PITCH 33          // conflict-free for scatter, compute, and gather
#define WPB 8             // warps per block
#define NBLK 592          // 4 * 148 blocks for BOTH kernels (same group split)

// Device-global scratch (no allocations allowed). Partials are fully
// overwritten by minmax_kernel every call -> no init kernel needed.
__device__ float g_pmn[NBLK];
__device__ float g_pmx[NBLK];

// Balanced contiguous split of G groups over nb blocks (identical in both
// kernels so block b touches the same data in both passes).
__device__ __forceinline__ void block_span(int G, int b, int nb,
                                           int& strt, int& cnt) {
    int base = G / nb, rem = G % nb;
    cnt  = base + (b < rem);
    strt = b * base + min(b, rem);
}

// Min/max pass. SAME warp->group mapping and SAME float4 access pattern as
// the recurrence kernel, but sweeping k DESCENDING. At kernel end, L2's most
// recent ~126MB = the LOW-k chunks of every group -> the recurrence kernel
// (k ascending) gets L2 hits on its first chunks.
__global__ void __launch_bounds__(WPB * 32) minmax_kernel(
        const float* __restrict__ in, int rows) {
    const int tid  = threadIdx.x;
    const int lane = tid & 31;
    const int warp = tid >> 5;

    const int G = rows >> 5;
    int strt, cnt;
    block_span(G, blockIdx.x, gridDim.x, strt, cnt);

    float mn =  CUDART_INF_F;
    float mx = -CUDART_INF_F;

    if (warp < cnt) {
        const int wgid = strt + warp;
        const float* __restrict__ inw = in + (size_t)wgid * 32 * N_DIM;
        const int my_col4x4 = (lane & 7) * 4;
        const int row_off   = lane >> 3;

        #pragma unroll 1
        for (int c = NCHUNK - 1; c >= 0; c--) {      // k-descending sweep
            const int k0 = c * KCH;
            #pragma unroll                            // 8 LDG.128 in flight
            for (int t = 0; t < 8; t++) {
                int r = t * 4 + row_off;
                float4 v = *(const float4*)(inw + (size_t)r * N_DIM + k0 + my_col4x4);
                mn = fminf(mn, fminf(fminf(v.x, v.y), fminf(v.z, v.w)));
                mx = fmaxf(mx, fmaxf(fmaxf(v.x, v.y), fmaxf(v.z, v.w)));
            }
        }
    }

    #pragma unroll
    for (int o = 16; o > 0; o >>= 1) {
        mn = fminf(mn, __shfl_xor_sync(0xFFFFFFFFu, mn, o));
        mx = fmaxf(mx, __shfl_xor_sync(0xFFFFFFFFu, mx, o));
    }
    __shared__ float smn[WPB], smx[WPB];
    if (lane == 0) { smn[warp] = mn; smx[warp] = mx; }
    __syncthreads();
    if (tid == 0) {
        float bmn = smn[0], bmx = smx[0];
        #pragma unroll
        for (int k = 1; k < WPB; k++) {
            bmn = fminf(bmn, smn[k]);
            bmx = fmaxf(bmx, smx[k]);
        }
        g_pmn[blockIdx.x] = bmn;   // deterministic overwrite, no atomics
        g_pmx[blockIdx.x] = bmx;
    }
}

// Warp-tiled recurrence (R8 structure: register prefetch pipeline, one
// 32-row group per warp, balanced split). New: xn is precomputed during the
// scatter phase (bit-identical value, hides 2 ops/step in the LDG shadow),
// and the first chunks of every group hit L2 thanks to minmax's descending
// sweep.
__global__ void __launch_bounds__(WPB * 32) recur_kernel(
        const float* __restrict__ in,
        const float* __restrict__ alpha,
        const float* __restrict__ beta,
        float* __restrict__ out,
        int rows) {
    __shared__ float tile_s[WPB][32 * PITCH];
    __shared__ float s_red[2 * WPB];
    __shared__ float s_mn, s_mx;

    const int tid  = threadIdx.x;
    const int lane = tid & 31;
    const int warp = tid >> 5;

    // ---- Prologue: every block reduces the minmax partials itself ----
    {
        float mn =  CUDART_INF_F;
        float mx = -CUDART_INF_F;
        for (int i = tid; i < NBLK; i += WPB * 32) {
            mn = fminf(mn, g_pmn[i]);
            mx = fmaxf(mx, g_pmx[i]);
        }
        #pragma unroll
        for (int o = 16; o > 0; o >>= 1) {
            mn = fminf(mn, __shfl_xor_sync(0xFFFFFFFFu, mn, o));
            mx = fmaxf(mx, __shfl_xor_sync(0xFFFFFFFFu, mx, o));
        }
        if (lane == 0) { s_red[warp] = mn; s_red[WPB + warp] = mx; }
        __syncthreads();
        if (tid == 0) {
            float bmn = s_red[0], bmx = s_red[WPB];
            #pragma unroll
            for (int k = 1; k < WPB; k++) {
                bmn = fminf(bmn, s_red[k]);
                bmx = fmaxf(bmx, s_red[WPB + k]);
            }
            s_mn = bmn; s_mx = bmx;
        }
        __syncthreads();
    }

    const int G = rows >> 5;
    int strt, cnt;
    block_span(G, blockIdx.x, gridDim.x, strt, cnt);
    if (warp >= cnt) return;
    const int wgid = strt + warp;

    float* tile = tile_s[warp];

    const float mn  = s_mn;
    const float rng = __fsub_rn(s_mx, mn);
    const float inv = __fdiv_rn(1.0f, rng);   // == div-by-rng bitwise (verified R2/R3)
    const float a   = alpha[0];
    const float nb  = -beta[0];

    const size_t bse = (size_t)wgid * 32 * N_DIM;
    const float* __restrict__ inw  = in  + bse;
    float* __restrict__       outw = out + bse;

    // float4 I/O pattern: lanes 0-7 = one row's 128B chunk, 4 rows per instr.
    const int my_col4x4 = (lane & 7) * 4;
    const int row_off   = lane >> 3;

    // normalize a float4 in place (bit-identical to per-step computation)
    #define NORM4(v) do {                                     \
        (v).x = __fmul_rn(__fsub_rn((v).x, mn), inv);          \
        (v).y = __fmul_rn(__fsub_rn((v).y, mn), inv);          \
        (v).z = __fmul_rn(__fsub_rn((v).z, mn), inv);          \
        (v).w = __fmul_rn(__fsub_rn((v).w, mn), inv);          \
    } while (0)

    // Prologue: load chunk 0 (LDG.128, coalesced).
    float4 q[8];
    #pragma unroll
    for (int t = 0; t < 8; t++) {
        int r = t * 4 + row_off;
        q[t] = *(const float4*)(inw + (size_t)r * N_DIM + my_col4x4);
    }

    float w = 1.0f;

    #pragma unroll 1
    for (int c = 0; c < NCHUNK; c++) {
        // Normalize + scatter current chunk -> smem (conflict-free, pitch 33).
        #pragma unroll
        for (int t = 0; t < 8; t++) {
            int r = t * 4 + row_off;
            float4 v = q[t];
            NORM4(v);
            float* p = tile + r * PITCH + my_col4x4;
            p[0] = v.x; p[1] = v.y; p[2] = v.z; p[3] = v.w;
        }
        __syncwarp();

        // Issue next chunk's LDG.128s; they overlap the compute below.
        if (c + 1 < NCHUNK) {
            const int k0n = (c + 1) * KCH;
            #pragma unroll
            for (int t = 0; t < 8; t++) {
                int r = t * 4 + row_off;
                q[t] = *(const float4*)(inw + (size_t)r * N_DIM + k0n + my_col4x4);
            }
        }

        // Serial recurrence: lane = row; tile holds pre-normalized xn.
        //   w' = fma(-b, xn, w + (a / w)) ; out[:,k] is the pre-step w.
        #pragma unroll
        for (int kk = 0; kk < KCH; kk++) {
            float xn = tile[lane * PITCH + kk];
            tile[lane * PITCH + kk] = w;
            w = __fmaf_rn(nb, xn, __fadd_rn(w, __fdiv_rn(a, w)));
        }
        __syncwarp();

        // Gather w values from smem and store as STG.128 (coalesced).
        const int k0 = c * KCH;
        #pragma unroll
        for (int t = 0; t < 8; t++) {
            int r = t * 4 + row_off;
            const float* p = tile + r * PITCH + my_col4x4;
            float4 o;
            o.x = p[0]; o.y = p[1]; o.z = p[2]; o.w = p[3];
            *(float4*)(outw + (size_t)r * N_DIM + k0 + my_col4x4) = o;
        }
        __syncwarp();
    }
    #undef NORM4
}

extern "C" void kernel_launch(void* const* d_in, const int* in_sizes, int n_in,
                              void* d_out, int out_size) {
    const float* in    = (const float*)d_in[0];
    const float* alpha = (const float*)d_in[1];
    const float* beta  = (const float*)d_in[2];
    float* out = (float*)d_out;

    long long n_elems = (long long)in_sizes[0];
    int rows = (int)(n_elems / N_DIM);

    minmax_kernel<<<NBLK, WPB * 32>>>(in, rows);
    recur_kernel<<<NBLK, WPB * 32>>>(in, alpha, beta, out, rows);
}

// round 13
// speedup vs baseline: 1.2549x; 1.0091x over previous
#include <cuda_runtime.h>
#include <math_constants.h>

#define N_DIM 512
#define KCH 32            // k-chunk per tile pass
#define NCHUNK (N_DIM / KCH)
#define PITCH 33          // conflict-free for scatter, compute, and gather
#define WPB 8             // warps per block
#define NBLK 592          // 4 * 148: every block resident -> spin barrier safe

// Device-global scratch (no allocations allowed). Partials are fully
// overwritten every call; the ticket is monotonic across graph replays.
__device__ float g_pmn[NBLK];
__device__ float g_pmx[NBLK];
__device__ unsigned long long g_ticket;   // zero-init once at module load

// Balanced contiguous split of G groups over nb blocks.
__device__ __forceinline__ void block_span(int G, int b, int nb,
                                           int& strt, int& cnt) {
    int base = G / nb, rem = G % nb;
    cnt  = base + (b < rem);
    strt = b * base + min(b, rem);
}

// Fused min/max + recurrence persistent kernel.
// Phase A: block-local min/max over this block's span (k-DESCENDING so the
//          low-k chunks end up L2-resident for phase B's ascending sweep).
// Global barrier: monotonic ticket (all NBLK blocks are co-resident by
//          __launch_bounds__(256,4) + 34KB smem, so spinning is safe).
// Phase B: warp-tiled recurrence (R12 structure: q[8] LDG.128 prefetch,
//          xn precomputed in the LDG shadow, pitch-33 conflict-free tile).
__global__ void __launch_bounds__(WPB * 32, 4) fused_kernel(
        const float* __restrict__ in,
        const float* __restrict__ alpha,
        const float* __restrict__ beta,
        float* __restrict__ out,
        int rows) {
    __shared__ float tile_s[WPB][32 * PITCH];
    __shared__ float s_red[2 * WPB];
    __shared__ float s_mn, s_mx;

    const int tid  = threadIdx.x;
    const int lane = tid & 31;
    const int warp = tid >> 5;

    const int G = rows >> 5;
    int strt, cnt;
    block_span(G, blockIdx.x, gridDim.x, strt, cnt);

    const int my_col4x4 = (lane & 7) * 4;   // float4 I/O pattern
    const int row_off   = lane >> 3;        // lanes 0-7 = one row's 128B

    // ---------------- Phase A: block-local min/max ----------------
    {
        float mn =  CUDART_INF_F;
        float mx = -CUDART_INF_F;
        if (warp < cnt) {
            const int wgid = strt + warp;
            const float* __restrict__ inw = in + (size_t)wgid * 32 * N_DIM;
            #pragma unroll 1
            for (int c = NCHUNK - 1; c >= 0; c--) {     // k-descending
                const int k0 = c * KCH;
                #pragma unroll
                for (int t = 0; t < 8; t++) {
                    int r = t * 4 + row_off;
                    float4 v = *(const float4*)(inw + (size_t)r * N_DIM + k0 + my_col4x4);
                    mn = fminf(mn, fminf(fminf(v.x, v.y), fminf(v.z, v.w)));
                    mx = fmaxf(mx, fmaxf(fmaxf(v.x, v.y), fmaxf(v.z, v.w)));
                }
            }
        }
        #pragma unroll
        for (int o = 16; o > 0; o >>= 1) {
            mn = fminf(mn, __shfl_xor_sync(0xFFFFFFFFu, mn, o));
            mx = fmaxf(mx, __shfl_xor_sync(0xFFFFFFFFu, mx, o));
        }
        if (lane == 0) { s_red[warp] = mn; s_red[WPB + warp] = mx; }
        __syncthreads();
        if (tid == 0) {
            float bmn = s_red[0], bmx = s_red[WPB];
            #pragma unroll
            for (int k = 1; k < WPB; k++) {
                bmn = fminf(bmn, s_red[k]);
                bmx = fmaxf(bmx, s_red[WPB + k]);
            }
            g_pmn[blockIdx.x] = bmn;
            g_pmx[blockIdx.x] = bmx;
            __threadfence();                               // publish partials
            // Monotonic ticket barrier: replays serialize, so at call entry
            // ticket === 0 (mod NBLK); this call completes at the next
            // multiple of NBLK after my arrival.
            unsigned long long ret = atomicAdd(&g_ticket, 1ULL);
            unsigned long long target = ret - (ret % NBLK) + NBLK;
            volatile unsigned long long* tk = &g_ticket;
            while (*tk < target) __nanosleep(200);
        }
        __syncthreads();                                   // block joins
        __threadfence();                                   // acquire partials
    }

    // ---------------- Reduce all partials (per block) ----------------
    {
        float mn =  CUDART_INF_F;
        float mx = -CUDART_INF_F;
        for (int i = tid; i < NBLK; i += WPB * 32) {
            mn = fminf(mn, g_pmn[i]);
            mx = fmaxf(mx, g_pmx[i]);
        }
        #pragma unroll
        for (int o = 16; o > 0; o >>= 1) {
            mn = fminf(mn, __shfl_xor_sync(0xFFFFFFFFu, mn, o));
            mx = fmaxf(mx, __shfl_xor_sync(0xFFFFFFFFu, mx, o));
        }
        if (lane == 0) { s_red[warp] = mn; s_red[WPB + warp] = mx; }
        __syncthreads();
        if (tid == 0) {
            float bmn = s_red[0], bmx = s_red[WPB];
            #pragma unroll
            for (int k = 1; k < WPB; k++) {
                bmn = fminf(bmn, s_red[k]);
                bmx = fmaxf(bmx, s_red[WPB + k]);
            }
            s_mn = bmn; s_mx = bmx;
        }
        __syncthreads();
    }

    // ---------------- Phase B: warp-tiled recurrence ----------------
    if (warp >= cnt) return;
    const int wgid = strt + warp;

    float* tile = tile_s[warp];

    const float mn  = s_mn;
    const float rng = __fsub_rn(s_mx, mn);
    const float inv = __fdiv_rn(1.0f, rng);   // == div-by-rng bitwise (verified R2/R3)
    const float a   = alpha[0];
    const float nb  = -beta[0];

    const size_t bse = (size_t)wgid * 32 * N_DIM;
    const float* __restrict__ inw  = in  + bse;
    float* __restrict__       outw = out + bse;

    #define NORM4(v) do {                                     \
        (v).x = __fmul_rn(__fsub_rn((v).x, mn), inv);          \
        (v).y = __fmul_rn(__fsub_rn((v).y, mn), inv);          \
        (v).z = __fmul_rn(__fsub_rn((v).z, mn), inv);          \
        (v).w = __fmul_rn(__fsub_rn((v).w, mn), inv);          \
    } while (0)

    // Prologue: load chunk 0 (LDG.128, coalesced; low-k chunks are L2-hot).
    float4 q[8];
    #pragma unroll
    for (int t = 0; t < 8; t++) {
        int r = t * 4 + row_off;
        q[t] = *(const float4*)(inw + (size_t)r * N_DIM + my_col4x4);
    }

    float w = 1.0f;

    #pragma unroll 1
    for (int c = 0; c < NCHUNK; c++) {
        // Normalize + scatter current chunk -> smem (conflict-free, pitch 33).
        #pragma unroll
        for (int t = 0; t < 8; t++) {
            int r = t * 4 + row_off;
            float4 v = q[t];
            NORM4(v);
            float* p = tile + r * PITCH + my_col4x4;
            p[0] = v.x; p[1] = v.y; p[2] = v.z; p[3] = v.w;
        }
        __syncwarp();

        // Issue next chunk's LDG.128s; they overlap the compute below.
        if (c + 1 < NCHUNK) {
            const int k0n = (c + 1) * KCH;
            #pragma unroll
            for (int t = 0; t < 8; t++) {
                int r = t * 4 + row_off;
                q[t] = *(const float4*)(inw + (size_t)r * N_DIM + k0n + my_col4x4);
            }
        }

        // Serial recurrence: lane = row; tile holds pre-normalized xn.
        //   w' = fma(-b, xn, w + (a / w)) ; out[:,k] is the pre-step w.
        #pragma unroll
        for (int kk = 0; kk < KCH; kk++) {
            float xn = tile[lane * PITCH + kk];
            tile[lane * PITCH + kk] = w;
            w = __fmaf_rn(nb, xn, __fadd_rn(w, __fdiv_rn(a, w)));
        }
        __syncwarp();

        // Gather w values from smem and store as STG.128 (coalesced).
        const int k0 = c * KCH;
        #pragma unroll
        for (int t = 0; t < 8; t++) {
            int r = t * 4 + row_off;
            const float* p = tile + r * PITCH + my_col4x4;
            float4 o;
            o.x = p[0]; o.y = p[1]; o.z = p[2]; o.w = p[3];
            *(float4*)(outw + (size_t)r * N_DIM + k0 + my_col4x4) = o;
        }
        __syncwarp();
    }
    #undef NORM4
}

extern "C" void kernel_launch(void* const* d_in, const int* in_sizes, int n_in,
                              void* d_out, int out_size) {
    const float* in    = (const float*)d_in[0];
    const float* alpha = (const float*)d_in[1];
    const float* beta  = (const float*)d_in[2];
    float* out = (float*)d_out;

    long long n_elems = (long long)in_sizes[0];
    int rows = (int)(n_elems / N_DIM);

    fused_kernel<<<NBLK, WPB * 32>>>(in, alpha, beta, out, rows);
}

// round 14
// speedup vs baseline: 1.2785x; 1.0188x over previous
#include <cuda_runtime.h>
#include <math_constants.h>

#define N_DIM 512
#define KCH 32            // k-chunk per tile pass
#define NCHUNK (N_DIM / KCH)
#define PITCH 33          // conflict-free for scatter, compute, and gather
#define WPB 8             // warps per block
#define NBLK 592          // 4 * 148: every block resident -> spin barrier safe

// Device-global scratch (no allocations allowed). Partials are fully
// overwritten every call; the ticket is monotonic across graph replays.
__device__ float g_pmn[NBLK];
__device__ float g_pmx[NBLK];
__device__ unsigned long long g_ticket;   // zero-init once at module load

// Balanced contiguous split of G groups over nb blocks.
__device__ __forceinline__ void block_span(int G, int b, int nb,
                                           int& strt, int& cnt) {
    int base = G / nb, rem = G % nb;
    cnt  = base + (b < rem);
    strt = b * base + min(b, rem);
}

__global__ void __launch_bounds__(WPB * 32, 4) fused_kernel(
        const float* __restrict__ in,
        const float* __restrict__ alpha,
        const float* __restrict__ beta,
        float* __restrict__ out,
        int rows) {
    __shared__ float tile_s[WPB][32 * PITCH];
    __shared__ float s_red[2 * WPB];
    __shared__ float s_mn, s_mx;

    const int tid  = threadIdx.x;
    const int lane = tid & 31;
    const int warp = tid >> 5;

    const int G = rows >> 5;
    int strt, cnt;
    block_span(G, blockIdx.x, gridDim.x, strt, cnt);

    const int my_col4x4 = (lane & 7) * 4;   // float4 I/O pattern
    const int row_off   = lane >> 3;        // lanes 0-7 = one row's 128B

    const bool active = (warp < cnt);
    const int wgid = strt + (active ? warp : 0);
    const float* __restrict__ inw  = in  + (size_t)wgid * 32 * N_DIM;
    float* __restrict__       outw = out + (size_t)wgid * 32 * N_DIM;

    // ---------------- Phase A: block-local min/max ----------------
    {
        float mn0 =  CUDART_INF_F, mn1 =  CUDART_INF_F;
        float mx0 = -CUDART_INF_F, mx1 = -CUDART_INF_F;
        if (active) {
            // two chunks per iteration -> 16 LDG.128 in flight; still
            // k-descending overall so low-k data is L2/L1-hot at the end.
            #pragma unroll 1
            for (int c2 = NCHUNK - 2; c2 >= 0; c2 -= 2) {
                const int kA = (c2 + 1) * KCH;
                const int kB = c2 * KCH;
                float4 va[8], vb[8];
                #pragma unroll
                for (int t = 0; t < 8; t++) {
                    int r = t * 4 + row_off;
                    va[t] = *(const float4*)(inw + (size_t)r * N_DIM + kA + my_col4x4);
                    vb[t] = *(const float4*)(inw + (size_t)r * N_DIM + kB + my_col4x4);
                }
                #pragma unroll
                for (int t = 0; t < 8; t++) {
                    mn0 = fminf(mn0, fminf(fminf(va[t].x, va[t].y), fminf(va[t].z, va[t].w)));
                    mx0 = fmaxf(mx0, fmaxf(fmaxf(va[t].x, va[t].y), fmaxf(va[t].z, va[t].w)));
                    mn1 = fminf(mn1, fminf(fminf(vb[t].x, vb[t].y), fminf(vb[t].z, vb[t].w)));
                    mx1 = fmaxf(mx1, fmaxf(fmaxf(vb[t].x, vb[t].y), fmaxf(vb[t].z, vb[t].w)));
                }
            }
        }
        float mn = fminf(mn0, mn1);
        float mx = fmaxf(mx0, mx1);
        #pragma unroll
        for (int o = 16; o > 0; o >>= 1) {
            mn = fminf(mn, __shfl_xor_sync(0xFFFFFFFFu, mn, o));
            mx = fmaxf(mx, __shfl_xor_sync(0xFFFFFFFFu, mx, o));
        }
        if (lane == 0) { s_red[warp] = mn; s_red[WPB + warp] = mx; }
        __syncthreads();
        if (tid == 0) {
            float bmn = s_red[0], bmx = s_red[WPB];
            #pragma unroll
            for (int k = 1; k < WPB; k++) {
                bmn = fminf(bmn, s_red[k]);
                bmx = fmaxf(bmx, s_red[WPB + k]);
            }
            g_pmn[blockIdx.x] = bmn;
            g_pmx[blockIdx.x] = bmx;
            __threadfence();                               // publish partials
        }
    }

    // ---- Pre-barrier prefetch: chunk 0 for phase B (input-only; safe).
    // Phase A just read these addresses (k-descending ends at chunk 0),
    // so these are L1/L2 hits; fills the barrier idle time.
    float4 q[8];
    if (active) {
        #pragma unroll
        for (int t = 0; t < 8; t++) {
            int r = t * 4 + row_off;
            q[t] = *(const float4*)(inw + (size_t)r * N_DIM + my_col4x4);
        }
    }

    // ---- Global barrier: monotonic ticket (all NBLK blocks co-resident) ----
    if (tid == 0) {
        unsigned long long ret = atomicAdd(&g_ticket, 1ULL);
        unsigned long long target = ret - (ret % NBLK) + NBLK;
        volatile unsigned long long* tk = &g_ticket;
        while (*tk < target) __nanosleep(200);
    }
    __syncthreads();
    __threadfence();                                       // acquire partials

    // ---------------- Reduce all partials (per block) ----------------
    {
        float mn =  CUDART_INF_F;
        float mx = -CUDART_INF_F;
        for (int i = tid; i < NBLK; i += WPB * 32) {
            mn = fminf(mn, g_pmn[i]);
            mx = fmaxf(mx, g_pmx[i]);
        }
        #pragma unroll
        for (int o = 16; o > 0; o >>= 1) {
            mn = fminf(mn, __shfl_xor_sync(0xFFFFFFFFu, mn, o));
            mx = fmaxf(mx, __shfl_xor_sync(0xFFFFFFFFu, mx, o));
        }
        if (lane == 0) { s_red[warp] = mn; s_red[WPB + warp] = mx; }
        __syncthreads();
        if (tid == 0) {
            float bmn = s_red[0], bmx = s_red[WPB];
            #pragma unroll
            for (int k = 1; k < WPB; k++) {
                bmn = fminf(bmn, s_red[k]);
                bmx = fmaxf(bmx, s_red[WPB + k]);
            }
            s_mn = bmn; s_mx = bmx;
        }
        __syncthreads();
    }

    // ---------------- Phase B: warp-tiled recurrence ----------------
    if (!active) return;

    float* tile = tile_s[warp];

    const float mn  = s_mn;
    const float rng = __fsub_rn(s_mx, mn);
    const float inv = __fdiv_rn(1.0f, rng);   // == div-by-rng bitwise (verified R2/R3)
    const float a   = alpha[0];
    const float nb  = -beta[0];

    #define NORM4(v) do {                                     \
        (v).x = __fmul_rn(__fsub_rn((v).x, mn), inv);          \
        (v).y = __fmul_rn(__fsub_rn((v).y, mn), inv);          \
        (v).z = __fmul_rn(__fsub_rn((v).z, mn), inv);          \
        (v).w = __fmul_rn(__fsub_rn((v).w, mn), inv);          \
    } while (0)

    float w = 1.0f;

    #pragma unroll 1
    for (int c = 0; c < NCHUNK; c++) {
        // Normalize + scatter current chunk -> smem (conflict-free, pitch 33).
        #pragma unroll
        for (int t = 0; t < 8; t++) {
            int r = t * 4 + row_off;
            float4 v = q[t];
            NORM4(v);
            float* p = tile + r * PITCH + my_col4x4;
            p[0] = v.x; p[1] = v.y; p[2] = v.z; p[3] = v.w;
        }
        __syncwarp();

        // Issue next chunk's LDG.128s; they overlap the compute below.
        if (c + 1 < NCHUNK) {
            const int k0n = (c + 1) * KCH;
            #pragma unroll
            for (int t = 0; t < 8; t++) {
                int r = t * 4 + row_off;
                q[t] = *(const float4*)(inw + (size_t)r * N_DIM + k0n + my_col4x4);
            }
        }

        // Serial recurrence: lane = row; tile holds pre-normalized xn.
        //   w' = fma(-b, xn, w + (a / w)) ; out[:,k] is the pre-step w.
        #pragma unroll
        for (int kk = 0; kk < KCH; kk++) {
            float xn = tile[lane * PITCH + kk];
            tile[lane * PITCH + kk] = w;
            w = __fmaf_rn(nb, xn, __fadd_rn(w, __fdiv_rn(a, w)));
        }
        __syncwarp();

        // Gather w values from smem and store as STG.128 (coalesced).
        const int k0 = c * KCH;
        #pragma unroll
        for (int t = 0; t < 8; t++) {
            int r = t * 4 + row_off;
            const float* p = tile + r * PITCH + my_col4x4;
            float4 o;
            o.x = p[0]; o.y = p[1]; o.z = p[2]; o.w = p[3];
            *(float4*)(outw + (size_t)r * N_DIM + k0 + my_col4x4) = o;
        }
        __syncwarp();
    }
    #undef NORM4
}

extern "C" void kernel_launch(void* const* d_in, const int* in_sizes, int n_in,
                              void* d_out, int out_size) {
    const float* in    = (const float*)d_in[0];
    const float* alpha = (const float*)d_in[1];
    const float* beta  = (const float*)d_in[2];
    float* out = (float*)d_out;

    long long n_elems = (long long)in_sizes[0];
    int rows = (int)(n_elems / N_DIM);

    fused_kernel<<<NBLK, WPB * 32>>>(in, alpha, beta, out, rows);
}